// round 4
// baseline (speedup 1.0000x reference)
#include <cuda_runtime.h>

// ---------------------------------------------------------------------------
// Problem constants
// ---------------------------------------------------------------------------
constexpr int Bn  = 8;
constexpr int CH  = 128;
constexpr int H   = 80;
constexpr int W   = 80;
constexpr int HW  = H * W;
constexpr int MID = 16;
constexpr int KD  = CH * 9;          // 1152
constexpr float EPS = 1e-5f;

// ---------------------------------------------------------------------------
// Scratch (static __device__ globals — allocation-free per harness rules)
// ---------------------------------------------------------------------------
__device__ float g_h[Bn * CH * HW];
__device__ float g_off[Bn * 27 * HW];
__device__ float g_vals[(size_t)Bn * CH * 9 * HW];   // [b][c*9+k][y][x]
__device__ float g_iral[Bn * CH * HW];
__device__ float g_g1[Bn * MID * HW];
__device__ float g_gate[Bn * HW];

#define DEV __device__ __forceinline__
typedef unsigned long long ull;

DEV float sigm_(float x) { return 1.0f / (1.0f + __expf(-x)); }
DEV float silu_(float x) { return x * sigm_(x); }

// packed f32x2 helpers
DEV void ffma2(ull& d, ull a, ull b) {
    asm("fma.rn.f32x2 %0, %1, %2, %0;" : "+l"(d) : "l"(a), "l"(b));
}
DEV ull dup2(float w) { ull u; asm("mov.b64 %0, {%1, %1};" : "=l"(u) : "f"(w)); return u; }
DEV void unpack2(ull u, float& x, float& y) {
    asm("mov.b64 {%0, %1}, %2;" : "=f"(x), "=f"(y) : "l"(u));
}

// ---------------------------------------------------------------------------
// Input fetch per conv mode
//   MODE 0: concat(rgb, ir)            Cin=256, 3x3 -> g_h      (silu(v+b))
//   MODE 1: concat(g*iral, (1-g)*rgb)  Cin=256, 3x3 -> out      (silu(bn)+res)
//   MODE 3: g_h                        Cin=128, 3x3 -> g_off    (v+b)
// ---------------------------------------------------------------------------
template <int MODE>
DEV float fetch_in(const float* __restrict__ A, const float* __restrict__ Bp,
                   int b, int ci, int gy, int gx) {
    if (MODE == 0) {
        return (ci < CH) ? A[((b * CH + ci) * H + gy) * W + gx]
                         : Bp[((b * CH + (ci - CH)) * H + gy) * W + gx];
    } else if (MODE == 1) {
        float gv = g_gate[(b * H + gy) * W + gx];
        return (ci < CH) ? gv * g_iral[((b * CH + ci) * H + gy) * W + gx]
                         : (1.0f - gv) * A[((b * CH + (ci - CH)) * H + gy) * W + gx];
    } else {
        return g_h[((b * CH + ci) * H + gy) * W + gx];
    }
}

// ---------------------------------------------------------------------------
// 3x3 tiled conv, 2 output rows per block, packed f32x2 math.
// Sliding 7-wide input window: per (ci,ky) load vv[7] once, reuse across kx.
// ---------------------------------------------------------------------------
template <int MODE>
__global__ __launch_bounds__(256)
void conv_kernel(const float* __restrict__ A, const float* __restrict__ Bp,
                 const float* __restrict__ wgt,
                 const float* __restrict__ bias_or_bn,
                 const float* __restrict__ res_scale,
                 float* __restrict__ out_param) {
    constexpr int KS   = 3;
    constexpr int KS2  = 9;
    constexpr int CIN  = (MODE == 3) ? CH : 2 * CH;
    constexpr int COUT = (MODE == 3) ? 27 : CH;
    constexpr int RCO  = (MODE == 3) ? 2 : 4;
    constexpr int CO_TILE = 16 * RCO;
    constexpr int CO_PAD  = CO_TILE + 4;
    constexpr int CC   = 16;
    constexpr int S    = CC * KS2;
    constexpr int XW   = W + 2;

    extern __shared__ float sm[];
    float*  sW = sm;                                  // [S][CO_PAD]
    float2* sI = (float2*)(sm + S * CO_PAD);          // [CC][3][XW]

    const int tid = threadIdx.x;
    const int tco = tid & 15;
    const int tpx = tid >> 4;
    const int x0  = tpx * 5;
    const int b   = blockIdx.x / (H / 2);
    const int y0  = (blockIdx.x % (H / 2)) * 2;
    const int co_base = blockIdx.y * CO_TILE;

    ull acc[RCO][5];
#pragma unroll
    for (int r = 0; r < RCO; r++)
#pragma unroll
        for (int p = 0; p < 5; p++) acc[r][p] = 0ull;

    for (int ci0 = 0; ci0 < CIN; ci0 += CC) {
        __syncthreads();
        for (int idx = tid; idx < CO_TILE * S; idx += 256) {
            int co = idx / S;
            int s  = idx % S;
            int cog = co_base + co;
            float v = 0.0f;
            if (cog < COUT) v = wgt[cog * (CIN * KS2) + ci0 * KS2 + s];
            sW[s * CO_PAD + co] = v;
        }
        for (int idx = tid; idx < CC * KS * XW; idx += 256) {
            int ci  = idx / (KS * XW);
            int rem = idx % (KS * XW);
            int ry  = rem / XW;
            int xx  = rem % XW;
            float v0 = 0.0f, v1 = 0.0f;
            int gx  = xx - 1;
            int gy0 = y0 - 1 + ry;
            int gy1 = gy0 + 1;
            if (gx >= 0 && gx < W) {
                if (gy0 >= 0 && gy0 < H) v0 = fetch_in<MODE>(A, Bp, b, ci0 + ci, gy0, gx);
                if (gy1 < H)             v1 = fetch_in<MODE>(A, Bp, b, ci0 + ci, gy1, gx);
            }
            sI[(ci * KS + ry) * XW + xx] = make_float2(v0, v1);
        }
        __syncthreads();
        for (int ci = 0; ci < CC; ++ci) {
#pragma unroll
            for (int ky = 0; ky < 3; ky++) {
                // one 7-wide window feeds all three kx taps
                const ull* ip = reinterpret_cast<const ull*>(&sI[(ci * KS + ky) * XW + x0]);
                ull vv[7];
#pragma unroll
                for (int j = 0; j < 7; j++) vv[j] = ip[j];
#pragma unroll
                for (int kx = 0; kx < 3; kx++) {
                    const int s = ci * KS2 + ky * 3 + kx;
                    const float* wp = &sW[s * CO_PAD + tco * RCO];
                    ull w2[RCO];
                    if (RCO == 4) {
                        float4 w4 = *reinterpret_cast<const float4*>(wp);
                        w2[0] = dup2(w4.x); w2[1] = dup2(w4.y);
                        w2[2] = dup2(w4.z); w2[3] = dup2(w4.w);
                    } else {
                        float2 wv = *reinterpret_cast<const float2*>(wp);
                        w2[0] = dup2(wv.x); w2[1] = dup2(wv.y);
                    }
#pragma unroll
                    for (int p = 0; p < 5; p++)
#pragma unroll
                        for (int r = 0; r < RCO; r++) ffma2(acc[r][p], w2[r], vv[kx + p]);
                }
            }
        }
    }

    float* optr = (MODE == 0) ? g_h : (MODE == 3) ? g_off : out_param;
#pragma unroll
    for (int r = 0; r < RCO; r++) {
        int co = co_base + tco * RCO + r;
        if (co >= COUT) continue;
        float bnb, bns = 1.0f, rs = 0.0f;
        if (MODE == 1) {
            float gm = bias_or_bn[co];
            float bt = bias_or_bn[COUT + co];
            float mn = bias_or_bn[2 * COUT + co];
            float vr = bias_or_bn[3 * COUT + co];
            bns = gm * rsqrtf(vr + EPS);
            bnb = bt - mn * bns;
            rs  = *res_scale;
        } else {
            bnb = bias_or_bn[co];
        }
#pragma unroll
        for (int p = 0; p < 5; p++) {
            int x = x0 + p;
            int o0 = ((b * COUT + co) * H + y0) * W + x;
            int o1 = o0 + W;
            float a0, a1;
            unpack2(acc[r][p], a0, a1);
            if (MODE == 0) {
                optr[o0] = silu_(a0 + bnb);
                optr[o1] = silu_(a1 + bnb);
            } else if (MODE == 1) {
                optr[o0] = silu_(a0 * bns + bnb) + rs * g_iral[o0];
                optr[o1] = silu_(a1 * bns + bnb) + rs * g_iral[o1];
            } else {
                optr[o0] = a0 + bnb;
                optr[o1] = a1 + bnb;
            }
        }
    }
}

// ---------------------------------------------------------------------------
// DCN 1x1 conv (Cin=1152 -> 128), all 128 couts in one pass.
// 320 threads = 16 cout-groups x 20 px-groups (4 px). 2 rows per block.
// Per ci: 2x LDS.128 inputs + 2x LDS.128 weights + 32 FFMA2.
// ---------------------------------------------------------------------------
__global__ __launch_bounds__(320, 2)
void dcn_conv_kernel(const float* __restrict__ wgt,
                     const float* __restrict__ bias) {
    constexpr int CIN = KD;          // 1152
    constexpr int CC  = 32;
    constexpr int RCO = 8;
    constexpr int CO_PAD = 132;      // multiple of 4 -> float4-aligned rows

    __shared__ float  sW[CC * CO_PAD];    // 16896 B
    __shared__ float2 sI[CC * W];         // 20480 B

    const int tid = threadIdx.x;
    const int tco = tid & 15;
    const int tpx = tid >> 4;             // 0..19
    const int x0  = tpx * 4;
    const int b   = blockIdx.x / (H / 2);
    const int y0  = (blockIdx.x % (H / 2)) * 2;

    ull acc[RCO][4];
#pragma unroll
    for (int r = 0; r < RCO; r++)
#pragma unroll
        for (int p = 0; p < 4; p++) acc[r][p] = 0ull;

    const float* vbase = g_vals + (size_t)b * CIN * HW + (size_t)y0 * W;

    for (int ci0 = 0; ci0 < CIN; ci0 += CC) {
        __syncthreads();
        for (int idx = tid; idx < CH * CC; idx += 320) {
            int co = idx / CC;
            int s  = idx % CC;
            sW[s * CO_PAD + co] = wgt[co * CIN + ci0 + s];
        }
        for (int idx = tid; idx < CC * W; idx += 320) {
            int ci = idx / W;
            int xx = idx % W;
            const float* vp = vbase + (size_t)(ci0 + ci) * HW + xx;
            sI[ci * W + xx] = make_float2(vp[0], vp[W]);
        }
        __syncthreads();
        for (int ci = 0; ci < CC; ++ci) {
            const ulonglong2* ip = reinterpret_cast<const ulonglong2*>(&sI[ci * W + x0]);
            ulonglong2 q0 = ip[0], q1 = ip[1];
            ull vv[4] = { q0.x, q0.y, q1.x, q1.y };
            const float* wp = &sW[ci * CO_PAD + tco * RCO];
            float4 wa = *reinterpret_cast<const float4*>(wp);
            float4 wb = *reinterpret_cast<const float4*>(wp + 4);
            ull w2[8] = { dup2(wa.x), dup2(wa.y), dup2(wa.z), dup2(wa.w),
                          dup2(wb.x), dup2(wb.y), dup2(wb.z), dup2(wb.w) };
#pragma unroll
            for (int p = 0; p < 4; p++)
#pragma unroll
                for (int r = 0; r < RCO; r++) ffma2(acc[r][p], w2[r], vv[p]);
        }
    }

#pragma unroll
    for (int r = 0; r < RCO; r++) {
        int co = tco * RCO + r;
        float bs = __ldg(&bias[co]);
#pragma unroll
        for (int p = 0; p < 4; p++) {
            int x = x0 + p;
            int o0 = ((b * CH + co) * H + y0) * W + x;
            float a0, a1;
            unpack2(acc[r][p], a0, a1);
            g_iral[o0]     = a0 + bs;
            g_iral[o0 + W] = a1 + bs;
        }
    }
}

// ---------------------------------------------------------------------------
// Deformable bilinear sampling -> g_vals[b][c*9+k][y][x]
// ---------------------------------------------------------------------------
__global__ __launch_bounds__(256)
void deform_kernel(const float* __restrict__ ir) {
    const int blk   = blockIdx.x;
    const int ytile = blk % 27;
    const int bk    = blk / 27;
    const int k     = bk % 9;
    const int b     = bk / 9;
    const int tid   = threadIdx.x;
    if (tid >= 240) return;
    const int y = ytile * 3 + tid / 80;
    const int x = tid % 80;
    if (y >= H) return;

    const float* obase = g_off + (b * 27) * HW + y * W + x;
    float oy = obase[(2 * k) * HW];
    float ox = obase[(2 * k + 1) * HW];
    float m  = sigm_(obase[(18 + k) * HW]);

    const int ky = k / 3 - 1;
    const int kx = k % 3 - 1;
    float ys = oy + (float)(ky + y);
    float xs = ox + (float)(kx + x);
    float fy = floorf(ys), fx = floorf(xs);
    float wy = ys - fy,    wx = xs - fx;
    int y0 = (int)fy, x0 = (int)fx;
    int y1 = y0 + 1,  x1 = x0 + 1;
    bool vy0 = (y0 >= 0) && (y0 < H);
    bool vy1 = (y1 >= 0) && (y1 < H);
    bool vx0 = (x0 >= 0) && (x0 < W);
    bool vx1 = (x1 >= 0) && (x1 < W);
    float w00 = (1.0f - wy) * (1.0f - wx) * m * ((vy0 && vx0) ? 1.0f : 0.0f);
    float w01 = (1.0f - wy) * wx          * m * ((vy0 && vx1) ? 1.0f : 0.0f);
    float w10 = wy          * (1.0f - wx) * m * ((vy1 && vx0) ? 1.0f : 0.0f);
    float w11 = wy          * wx          * m * ((vy1 && vx1) ? 1.0f : 0.0f);
    int cy0 = min(max(y0, 0), H - 1), cy1 = min(max(y1, 0), H - 1);
    int cx0 = min(max(x0, 0), W - 1), cx1 = min(max(x1, 0), W - 1);
    int i00 = cy0 * W + cx0, i01 = cy0 * W + cx1;
    int i10 = cy1 * W + cx0, i11 = cy1 * W + cx1;

    const float* ib = ir + b * CH * HW;
    float* vout = g_vals + ((size_t)b * CH * 9 + k) * HW + y * W + x;
#pragma unroll 4
    for (int c = 0; c < CH; c++) {
        const float* p = ib + c * HW;
        float v = w00 * __ldg(p + i00) + w01 * __ldg(p + i01)
                + w10 * __ldg(p + i10) + w11 * __ldg(p + i11);
        vout[(size_t)c * 9 * HW] = v;
    }
}

// ---------------------------------------------------------------------------
// Gate stage 1: 1x1 conv 256 -> 16 + BN + SiLU -> g_g1
// ---------------------------------------------------------------------------
__global__ __launch_bounds__(256)
void gate1_kernel(const float* __restrict__ rgb,
                  const float* __restrict__ wg1,
                  const float* __restrict__ bng1) {
    __shared__ float sg[2 * CH * MID];
    const int tid = threadIdx.x;
    for (int i = tid; i < 2 * CH * MID; i += 256) {
        int ci = i >> 4, o = i & 15;
        sg[i] = wg1[o * (2 * CH) + ci];
    }
    __syncthreads();
    const int idx = blockIdx.x * 256 + tid;
    if (idx >= Bn * HW) return;
    const int b = idx / HW, p = idx % HW;

    float acc[MID];
#pragma unroll
    for (int o = 0; o < MID; o++) acc[o] = 0.0f;

    const float* rp = rgb    + b * CH * HW + p;
    const float* ip = g_iral + b * CH * HW + p;
    for (int ci = 0; ci < CH; ci++) {
        float v = rp[ci * HW];
        const float* w = &sg[ci * MID];
#pragma unroll
        for (int o = 0; o < MID; o++) acc[o] += w[o] * v;
    }
    for (int ci = 0; ci < CH; ci++) {
        float v = ip[ci * HW];
        const float* w = &sg[(CH + ci) * MID];
#pragma unroll
        for (int o = 0; o < MID; o++) acc[o] += w[o] * v;
    }
#pragma unroll
    for (int o = 0; o < MID; o++) {
        float gm = bng1[o], bt = bng1[MID + o];
        float mn = bng1[2 * MID + o], vr = bng1[3 * MID + o];
        float sc = gm * rsqrtf(vr + EPS);
        g_g1[(b * MID + o) * HW + p] = silu_(acc[o] * sc + bt - mn * sc);
    }
}

// ---------------------------------------------------------------------------
// Gate stages 2+3: depthwise 3x3 + BN + SiLU, then 1x1 16->1 + sigmoid
// ---------------------------------------------------------------------------
__global__ __launch_bounds__(256)
void gate23_kernel(const float* __restrict__ wg2,
                   const float* __restrict__ bng2,
                   const float* __restrict__ wg3,
                   const float* __restrict__ bg3) {
    const int idx = blockIdx.x * 256 + threadIdx.x;
    if (idx >= Bn * HW) return;
    const int b = idx / HW, p = idx % HW;
    const int y = p / W, x = p % W;

    float s3 = __ldg(bg3);
#pragma unroll
    for (int o = 0; o < MID; o++) {
        const float* gp = g_g1 + (b * MID + o) * HW;
        float s = 0.0f;
#pragma unroll
        for (int ky = 0; ky < 3; ky++) {
            int yy = y + ky - 1;
            if (yy < 0 || yy >= H) continue;
#pragma unroll
            for (int kx = 0; kx < 3; kx++) {
                int xx = x + kx - 1;
                if (xx < 0 || xx >= W) continue;
                s += gp[yy * W + xx] * __ldg(&wg2[o * 9 + ky * 3 + kx]);
            }
        }
        float gm = __ldg(&bng2[o]), bt = __ldg(&bng2[MID + o]);
        float mn = __ldg(&bng2[2 * MID + o]), vr = __ldg(&bng2[3 * MID + o]);
        float sc = gm * rsqrtf(vr + EPS);
        s3 += silu_(s * sc + bt - mn * sc) * __ldg(&wg3[o]);
    }
    g_gate[b * HW + p] = sigm_(s3);
}

// ---------------------------------------------------------------------------
// Launcher
// ---------------------------------------------------------------------------
extern "C" void kernel_launch(void* const* d_in, const int* in_sizes, int n_in,
                              void* d_out, int out_size) {
    const float* rgb    = (const float*)d_in[0];
    const float* ir     = (const float*)d_in[1];
    const float* w_off1 = (const float*)d_in[2];
    const float* b_off1 = (const float*)d_in[3];
    const float* w_off2 = (const float*)d_in[4];
    const float* b_off2 = (const float*)d_in[5];
    const float* w_dcn  = (const float*)d_in[6];
    const float* b_dcn  = (const float*)d_in[7];
    const float* w_g1   = (const float*)d_in[8];
    const float* bn_g1  = (const float*)d_in[9];
    const float* w_g2   = (const float*)d_in[10];
    const float* bn_g2  = (const float*)d_in[11];
    const float* w_g3   = (const float*)d_in[12];
    const float* b_g3   = (const float*)d_in[13];
    const float* w_f    = (const float*)d_in[14];
    const float* bn_f   = (const float*)d_in[15];
    const float* rscale = (const float*)d_in[16];
    float* out = (float*)d_out;

    const int sm_big = (144 * 68) * 4 + (16 * 3 * 82) * 8;   // modes 0,1
    const int sm_off = (144 * 36) * 4 + (16 * 3 * 82) * 8;   // mode 3

    cudaFuncSetAttribute(conv_kernel<0>, cudaFuncAttributeMaxDynamicSharedMemorySize, sm_big);
    cudaFuncSetAttribute(conv_kernel<1>, cudaFuncAttributeMaxDynamicSharedMemorySize, sm_big);
    cudaFuncSetAttribute(conv_kernel<3>, cudaFuncAttributeMaxDynamicSharedMemorySize, sm_off);

    const int BX = Bn * (H / 2);   // 320 row-pair blocks

    // 1) h = silu(conv3x3(concat(rgb, ir)))
    conv_kernel<0><<<dim3(BX, 2), 256, sm_big>>>(rgb, ir, w_off1, b_off1, nullptr, nullptr);
    // 2) offset/mask conv (27 ch)
    conv_kernel<3><<<dim3(BX, 1), 256, sm_off>>>(nullptr, nullptr, w_off2, b_off2, nullptr, nullptr);
    // 3) deformable bilinear sampling * mask -> g_vals
    deform_kernel<<<Bn * 9 * 27, 256>>>(ir);
    // 4) ir_aligned = vals . w_dcn + b_dcn (1x1 conv, Cin=1152, 128 couts/pass)
    dcn_conv_kernel<<<BX, 320>>>(w_dcn, b_dcn);
    // 5) gate stage 1
    gate1_kernel<<<(Bn * HW + 255) / 256, 256>>>(rgb, w_g1, bn_g1);
    // 6) gate stages 2+3
    gate23_kernel<<<(Bn * HW + 255) / 256, 256>>>(w_g2, bn_g2, w_g3, b_g3);
    // 7) fused conv + BN + SiLU + residual -> out
    conv_kernel<1><<<dim3(BX, 2), 256, sm_big>>>(rgb, nullptr, w_f, bn_f, rscale, out);
}

// round 5
// speedup vs baseline: 1.0645x; 1.0645x over previous
#include <cuda_runtime.h>

// ---------------------------------------------------------------------------
// Problem constants
// ---------------------------------------------------------------------------
constexpr int Bn  = 8;
constexpr int CH  = 128;
constexpr int H   = 80;
constexpr int W   = 80;
constexpr int HW  = H * W;
constexpr int MID = 16;
constexpr int KD  = CH * 9;          // 1152
constexpr float EPS = 1e-5f;

// ---------------------------------------------------------------------------
// Scratch
// ---------------------------------------------------------------------------
__device__ float g_h[Bn * CH * HW];
__device__ float g_off[Bn * 27 * HW];
__device__ float g_vals[(size_t)Bn * CH * 9 * HW];   // [b][c*9+k][y][x]
__device__ float g_iral[Bn * CH * HW];
__device__ float g_g1[Bn * MID * HW];
__device__ float g_gate[Bn * HW];

#define DEV __device__ __forceinline__
typedef unsigned long long ull;
typedef unsigned int u32;

DEV float sigm_(float x) { return 1.0f / (1.0f + __expf(-x)); }
DEV float silu_(float x) { return x * sigm_(x); }

DEV void ffma2(ull& d, ull a, ull b) {
    asm("fma.rn.f32x2 %0, %1, %2, %0;" : "+l"(d) : "l"(a), "l"(b));
}
DEV ull dup2(float w) { ull u; asm("mov.b64 %0, {%1, %1};" : "=l"(u) : "f"(w)); return u; }
DEV void unpack2(ull u, float& x, float& y) {
    asm("mov.b64 {%0, %1}, %2;" : "=f"(x), "=f"(y) : "l"(u));
}
DEV u32 smem_u32(const void* p) {
    u32 a; asm("{ .reg .u64 t; cvta.to.shared.u64 t, %1; cvt.u32.u64 %0, t; }" : "=r"(a) : "l"(p));
    return a;
}
DEV void cp4(u32 dst, const float* src) {
    asm volatile("cp.async.ca.shared.global [%0], [%1], 4;" :: "r"(dst), "l"(src) : "memory");
}
DEV void cp_commit() { asm volatile("cp.async.commit_group;" ::: "memory"); }
DEV void cp_wait1()  { asm volatile("cp.async.wait_group 1;" ::: "memory"); }
DEV void cp_wait0()  { asm volatile("cp.async.wait_group 0;" ::: "memory"); }

// ---------------------------------------------------------------------------
// Input fetch per conv mode (3x3 kernels)
// ---------------------------------------------------------------------------
template <int MODE>
DEV float fetch_in(const float* __restrict__ A, const float* __restrict__ Bp,
                   int b, int ci, int gy, int gx) {
    if (MODE == 0) {
        return (ci < CH) ? A[((b * CH + ci) * H + gy) * W + gx]
                         : Bp[((b * CH + (ci - CH)) * H + gy) * W + gx];
    } else if (MODE == 1) {
        float gv = g_gate[(b * H + gy) * W + gx];
        return (ci < CH) ? gv * g_iral[((b * CH + ci) * H + gy) * W + gx]
                         : (1.0f - gv) * A[((b * CH + (ci - CH)) * H + gy) * W + gx];
    } else {
        return g_h[((b * CH + ci) * H + gy) * W + gx];
    }
}

// ---------------------------------------------------------------------------
// 3x3 tiled conv, 2 output rows per block, packed f32x2, sliding 7-wide window
// ---------------------------------------------------------------------------
template <int MODE>
__global__ __launch_bounds__(256)
void conv_kernel(const float* __restrict__ A, const float* __restrict__ Bp,
                 const float* __restrict__ wgt,
                 const float* __restrict__ bias_or_bn,
                 const float* __restrict__ res_scale,
                 float* __restrict__ out_param) {
    constexpr int KS   = 3;
    constexpr int KS2  = 9;
    constexpr int CIN  = (MODE == 3) ? CH : 2 * CH;
    constexpr int COUT = (MODE == 3) ? 27 : CH;
    constexpr int RCO  = (MODE == 3) ? 2 : 4;
    constexpr int CO_TILE = 16 * RCO;
    constexpr int CO_PAD  = CO_TILE + 4;
    constexpr int CC   = 16;
    constexpr int S    = CC * KS2;
    constexpr int XW   = W + 2;

    extern __shared__ float sm[];
    float*  sW = sm;                                  // [S][CO_PAD]
    float2* sI = (float2*)(sm + S * CO_PAD);          // [CC][3][XW]

    const int tid = threadIdx.x;
    const int tco = tid & 15;
    const int tpx = tid >> 4;
    const int x0  = tpx * 5;
    const int b   = blockIdx.x / (H / 2);
    const int y0  = (blockIdx.x % (H / 2)) * 2;
    const int co_base = blockIdx.y * CO_TILE;

    ull acc[RCO][5];
#pragma unroll
    for (int r = 0; r < RCO; r++)
#pragma unroll
        for (int p = 0; p < 5; p++) acc[r][p] = 0ull;

    for (int ci0 = 0; ci0 < CIN; ci0 += CC) {
        __syncthreads();
        for (int idx = tid; idx < CO_TILE * S; idx += 256) {
            int co = idx / S;
            int s  = idx % S;
            int cog = co_base + co;
            float v = 0.0f;
            if (cog < COUT) v = wgt[cog * (CIN * KS2) + ci0 * KS2 + s];
            sW[s * CO_PAD + co] = v;
        }
        for (int idx = tid; idx < CC * KS * XW; idx += 256) {
            int ci  = idx / (KS * XW);
            int rem = idx % (KS * XW);
            int ry  = rem / XW;
            int xx  = rem % XW;
            float v0 = 0.0f, v1 = 0.0f;
            int gx  = xx - 1;
            int gy0 = y0 - 1 + ry;
            int gy1 = gy0 + 1;
            if (gx >= 0 && gx < W) {
                if (gy0 >= 0 && gy0 < H) v0 = fetch_in<MODE>(A, Bp, b, ci0 + ci, gy0, gx);
                if (gy1 < H)             v1 = fetch_in<MODE>(A, Bp, b, ci0 + ci, gy1, gx);
            }
            sI[(ci * KS + ry) * XW + xx] = make_float2(v0, v1);
        }
        __syncthreads();
        for (int ci = 0; ci < CC; ++ci) {
#pragma unroll
            for (int ky = 0; ky < 3; ky++) {
                const ull* ip = reinterpret_cast<const ull*>(&sI[(ci * KS + ky) * XW + x0]);
                ull vv[7];
#pragma unroll
                for (int j = 0; j < 7; j++) vv[j] = ip[j];
#pragma unroll
                for (int kx = 0; kx < 3; kx++) {
                    const int s = ci * KS2 + ky * 3 + kx;
                    const float* wp = &sW[s * CO_PAD + tco * RCO];
                    ull w2[RCO];
                    if (RCO == 4) {
                        float4 w4 = *reinterpret_cast<const float4*>(wp);
                        w2[0] = dup2(w4.x); w2[1] = dup2(w4.y);
                        w2[2] = dup2(w4.z); w2[3] = dup2(w4.w);
                    } else {
                        float2 wv = *reinterpret_cast<const float2*>(wp);
                        w2[0] = dup2(wv.x); w2[1] = dup2(wv.y);
                    }
#pragma unroll
                    for (int p = 0; p < 5; p++)
#pragma unroll
                        for (int r = 0; r < RCO; r++) ffma2(acc[r][p], w2[r], vv[kx + p]);
                }
            }
        }
    }

    float* optr = (MODE == 0) ? g_h : (MODE == 3) ? g_off : out_param;
#pragma unroll
    for (int r = 0; r < RCO; r++) {
        int co = co_base + tco * RCO + r;
        if (co >= COUT) continue;
        float bnb, bns = 1.0f, rs = 0.0f;
        if (MODE == 1) {
            float gm = bias_or_bn[co];
            float bt = bias_or_bn[COUT + co];
            float mn = bias_or_bn[2 * COUT + co];
            float vr = bias_or_bn[3 * COUT + co];
            bns = gm * rsqrtf(vr + EPS);
            bnb = bt - mn * bns;
            rs  = *res_scale;
        } else {
            bnb = bias_or_bn[co];
        }
#pragma unroll
        for (int p = 0; p < 5; p++) {
            int x = x0 + p;
            int o0 = ((b * COUT + co) * H + y0) * W + x;
            int o1 = o0 + W;
            float a0, a1;
            unpack2(acc[r][p], a0, a1);
            if (MODE == 0) {
                optr[o0] = silu_(a0 + bnb);
                optr[o1] = silu_(a1 + bnb);
            } else if (MODE == 1) {
                optr[o0] = silu_(a0 * bns + bnb) + rs * g_iral[o0];
                optr[o1] = silu_(a1 * bns + bnb) + rs * g_iral[o1];
            } else {
                optr[o0] = a0 + bnb;
                optr[o1] = a1 + bnb;
            }
        }
    }
}

// ---------------------------------------------------------------------------
// DCN 1x1 conv (Cin=1152 -> 128), cp.async double-buffered pipeline.
// R2 geometry: 256 thr = 16 co-groups x 16 px-groups (5 px), 2 rows,
// CO_TILE=64, grid (320, 2). 36 k-chunks of CC=32.
// ---------------------------------------------------------------------------
constexpr int DCC     = 32;
constexpr int DCO_T   = 64;
constexpr int DCO_PAD = 68;
constexpr int DWELEM  = DCO_T * DCC;          // 2048 weight elems / chunk
constexpr int DIELEM  = DCC * W;              // 2560 input pairs / chunk
constexpr int DSM_W   = DCC * DCO_PAD;        // floats per weight buffer
constexpr int DSM_I   = DCC * W;              // float2 per input buffer
constexpr int DCN_SMEM = (2 * DSM_W) * 4 + (2 * DSM_I) * 8;   // 58368 B

__global__ __launch_bounds__(256)
void dcn_conv_kernel(const float* __restrict__ wgt,
                     const float* __restrict__ bias) {
    extern __shared__ float dsm[];
    float*  sW = dsm;                              // [2][DSM_W]
    float2* sI = (float2*)(dsm + 2 * DSM_W);       // [2][DSM_I]

    const int tid = threadIdx.x;
    const int tco = tid & 15;
    const int tpx = tid >> 4;
    const int x0  = tpx * 5;
    const int b   = blockIdx.x / (H / 2);
    const int y0  = (blockIdx.x % (H / 2)) * 2;
    const int co_base = blockIdx.y * DCO_T;

    const u32 swb = smem_u32(sW);
    const u32 sib = smem_u32(sI);
    const float* vbase = g_vals + (size_t)b * KD * HW + (size_t)y0 * W;

    ull acc[4][5];
#pragma unroll
    for (int r = 0; r < 4; r++)
#pragma unroll
        for (int p = 0; p < 5; p++) acc[r][p] = 0ull;

    // async stage of one chunk into buffer `buf`
    auto stage = [&](int ck, int buf) {
        const int ci0 = ck * DCC;
        // weights: 2048 elems, 8 per thread
#pragma unroll
        for (int i = 0; i < DWELEM / 256; i++) {
            int idx = i * 256 + tid;
            int co = idx >> 5, s = idx & 31;
            u32 dst = swb + (u32)(buf * DSM_W + s * DCO_PAD + co) * 4u;
            cp4(dst, wgt + (size_t)(co_base + co) * KD + ci0 + s);
        }
        // inputs: 2560 (row0,row1) pairs, 10 per thread, 2 x 4B cp.async each
#pragma unroll
        for (int i = 0; i < DIELEM / 256; i++) {
            int idx = i * 256 + tid;
            int ci = idx / W, xx = idx % W;
            const float* src = vbase + (size_t)(ci0 + ci) * HW + xx;
            u32 dst = sib + (u32)(buf * DSM_I + ci * W + xx) * 8u;
            cp4(dst, src);
            cp4(dst + 4, src + W);
        }
        cp_commit();
    };

    stage(0, 0);

    constexpr int NCK = KD / DCC;   // 36
    for (int ck = 0; ck < NCK; ck++) {
        const int buf = ck & 1;
        if (ck + 1 < NCK) { stage(ck + 1, buf ^ 1); cp_wait1(); }
        else              { cp_wait0(); }
        __syncthreads();

        const float*  wbuf = sW + buf * DSM_W;
        const float2* ibuf = sI + buf * DSM_I;
#pragma unroll 4
        for (int ci = 0; ci < DCC; ++ci) {
            const ull* ip = reinterpret_cast<const ull*>(&ibuf[ci * W + x0]);
            ull vv[5];
#pragma unroll
            for (int p = 0; p < 5; p++) vv[p] = ip[p];
            float4 w4 = *reinterpret_cast<const float4*>(&wbuf[ci * DCO_PAD + tco * 4]);
            ull w2[4] = { dup2(w4.x), dup2(w4.y), dup2(w4.z), dup2(w4.w) };
#pragma unroll
            for (int p = 0; p < 5; p++)
#pragma unroll
                for (int r = 0; r < 4; r++) ffma2(acc[r][p], w2[r], vv[p]);
        }
        __syncthreads();
    }

#pragma unroll
    for (int r = 0; r < 4; r++) {
        int co = co_base + tco * 4 + r;
        float bs = __ldg(&bias[co]);
#pragma unroll
        for (int p = 0; p < 5; p++) {
            int x = x0 + p;
            int o0 = ((b * CH + co) * H + y0) * W + x;
            float a0, a1;
            unpack2(acc[r][p], a0, a1);
            g_iral[o0]     = a0 + bs;
            g_iral[o0 + W] = a1 + bs;
        }
    }
}

// ---------------------------------------------------------------------------
// Deformable bilinear sampling -> g_vals[b][c*9+k][y][x]
// ---------------------------------------------------------------------------
__global__ __launch_bounds__(256)
void deform_kernel(const float* __restrict__ ir) {
    const int blk   = blockIdx.x;
    const int ytile = blk % 27;
    const int bk    = blk / 27;
    const int k     = bk % 9;
    const int b     = bk / 9;
    const int tid   = threadIdx.x;
    if (tid >= 240) return;
    const int y = ytile * 3 + tid / 80;
    const int x = tid % 80;
    if (y >= H) return;

    const float* obase = g_off + (b * 27) * HW + y * W + x;
    float oy = obase[(2 * k) * HW];
    float ox = obase[(2 * k + 1) * HW];
    float m  = sigm_(obase[(18 + k) * HW]);

    const int ky = k / 3 - 1;
    const int kx = k % 3 - 1;
    float ys = oy + (float)(ky + y);
    float xs = ox + (float)(kx + x);
    float fy = floorf(ys), fx = floorf(xs);
    float wy = ys - fy,    wx = xs - fx;
    int y0 = (int)fy, x0 = (int)fx;
    int y1 = y0 + 1,  x1 = x0 + 1;
    bool vy0 = (y0 >= 0) && (y0 < H);
    bool vy1 = (y1 >= 0) && (y1 < H);
    bool vx0 = (x0 >= 0) && (x0 < W);
    bool vx1 = (x1 >= 0) && (x1 < W);
    float w00 = (1.0f - wy) * (1.0f - wx) * m * ((vy0 && vx0) ? 1.0f : 0.0f);
    float w01 = (1.0f - wy) * wx          * m * ((vy0 && vx1) ? 1.0f : 0.0f);
    float w10 = wy          * (1.0f - wx) * m * ((vy1 && vx0) ? 1.0f : 0.0f);
    float w11 = wy          * wx          * m * ((vy1 && vx1) ? 1.0f : 0.0f);
    int cy0 = min(max(y0, 0), H - 1), cy1 = min(max(y1, 0), H - 1);
    int cx0 = min(max(x0, 0), W - 1), cx1 = min(max(x1, 0), W - 1);
    int i00 = cy0 * W + cx0, i01 = cy0 * W + cx1;
    int i10 = cy1 * W + cx0, i11 = cy1 * W + cx1;

    const float* ib = ir + b * CH * HW;
    float* vout = g_vals + ((size_t)b * CH * 9 + k) * HW + y * W + x;
#pragma unroll 4
    for (int c = 0; c < CH; c++) {
        const float* p = ib + c * HW;
        float v = w00 * __ldg(p + i00) + w01 * __ldg(p + i01)
                + w10 * __ldg(p + i10) + w11 * __ldg(p + i11);
        vout[(size_t)c * 9 * HW] = v;
    }
}

// ---------------------------------------------------------------------------
// Gate stage 1: 1x1 conv 256 -> 16 + BN + SiLU -> g_g1
// ---------------------------------------------------------------------------
__global__ __launch_bounds__(256)
void gate1_kernel(const float* __restrict__ rgb,
                  const float* __restrict__ wg1,
                  const float* __restrict__ bng1) {
    __shared__ float sg[2 * CH * MID];
    const int tid = threadIdx.x;
    for (int i = tid; i < 2 * CH * MID; i += 256) {
        int ci = i >> 4, o = i & 15;
        sg[i] = wg1[o * (2 * CH) + ci];
    }
    __syncthreads();
    const int idx = blockIdx.x * 256 + tid;
    if (idx >= Bn * HW) return;
    const int b = idx / HW, p = idx % HW;

    float acc[MID];
#pragma unroll
    for (int o = 0; o < MID; o++) acc[o] = 0.0f;

    const float* rp = rgb    + b * CH * HW + p;
    const float* ip = g_iral + b * CH * HW + p;
    for (int ci = 0; ci < CH; ci++) {
        float v = rp[ci * HW];
        const float* w = &sg[ci * MID];
#pragma unroll
        for (int o = 0; o < MID; o++) acc[o] += w[o] * v;
    }
    for (int ci = 0; ci < CH; ci++) {
        float v = ip[ci * HW];
        const float* w = &sg[(CH + ci) * MID];
#pragma unroll
        for (int o = 0; o < MID; o++) acc[o] += w[o] * v;
    }
#pragma unroll
    for (int o = 0; o < MID; o++) {
        float gm = bng1[o], bt = bng1[MID + o];
        float mn = bng1[2 * MID + o], vr = bng1[3 * MID + o];
        float sc = gm * rsqrtf(vr + EPS);
        g_g1[(b * MID + o) * HW + p] = silu_(acc[o] * sc + bt - mn * sc);
    }
}

// ---------------------------------------------------------------------------
// Gate stages 2+3
// ---------------------------------------------------------------------------
__global__ __launch_bounds__(256)
void gate23_kernel(const float* __restrict__ wg2,
                   const float* __restrict__ bng2,
                   const float* __restrict__ wg3,
                   const float* __restrict__ bg3) {
    const int idx = blockIdx.x * 256 + threadIdx.x;
    if (idx >= Bn * HW) return;
    const int b = idx / HW, p = idx % HW;
    const int y = p / W, x = p % W;

    float s3 = __ldg(bg3);
#pragma unroll
    for (int o = 0; o < MID; o++) {
        const float* gp = g_g1 + (b * MID + o) * HW;
        float s = 0.0f;
#pragma unroll
        for (int ky = 0; ky < 3; ky++) {
            int yy = y + ky - 1;
            if (yy < 0 || yy >= H) continue;
#pragma unroll
            for (int kx = 0; kx < 3; kx++) {
                int xx = x + kx - 1;
                if (xx < 0 || xx >= W) continue;
                s += gp[yy * W + xx] * __ldg(&wg2[o * 9 + ky * 3 + kx]);
            }
        }
        float gm = __ldg(&bng2[o]), bt = __ldg(&bng2[MID + o]);
        float mn = __ldg(&bng2[2 * MID + o]), vr = __ldg(&bng2[3 * MID + o]);
        float sc = gm * rsqrtf(vr + EPS);
        s3 += silu_(s * sc + bt - mn * sc) * __ldg(&wg3[o]);
    }
    g_gate[b * HW + p] = sigm_(s3);
}

// ---------------------------------------------------------------------------
// Launcher
// ---------------------------------------------------------------------------
extern "C" void kernel_launch(void* const* d_in, const int* in_sizes, int n_in,
                              void* d_out, int out_size) {
    const float* rgb    = (const float*)d_in[0];
    const float* ir     = (const float*)d_in[1];
    const float* w_off1 = (const float*)d_in[2];
    const float* b_off1 = (const float*)d_in[3];
    const float* w_off2 = (const float*)d_in[4];
    const float* b_off2 = (const float*)d_in[5];
    const float* w_dcn  = (const float*)d_in[6];
    const float* b_dcn  = (const float*)d_in[7];
    const float* w_g1   = (const float*)d_in[8];
    const float* bn_g1  = (const float*)d_in[9];
    const float* w_g2   = (const float*)d_in[10];
    const float* bn_g2  = (const float*)d_in[11];
    const float* w_g3   = (const float*)d_in[12];
    const float* b_g3   = (const float*)d_in[13];
    const float* w_f    = (const float*)d_in[14];
    const float* bn_f   = (const float*)d_in[15];
    const float* rscale = (const float*)d_in[16];
    float* out = (float*)d_out;

    const int sm_big = (144 * 68) * 4 + (16 * 3 * 82) * 8;   // modes 0,1
    const int sm_off = (144 * 36) * 4 + (16 * 3 * 82) * 8;   // mode 3

    cudaFuncSetAttribute(conv_kernel<0>, cudaFuncAttributeMaxDynamicSharedMemorySize, sm_big);
    cudaFuncSetAttribute(conv_kernel<1>, cudaFuncAttributeMaxDynamicSharedMemorySize, sm_big);
    cudaFuncSetAttribute(conv_kernel<3>, cudaFuncAttributeMaxDynamicSharedMemorySize, sm_off);
    cudaFuncSetAttribute(dcn_conv_kernel, cudaFuncAttributeMaxDynamicSharedMemorySize, DCN_SMEM);

    const int BX = Bn * (H / 2);   // 320 row-pair blocks

    // 1) h = silu(conv3x3(concat(rgb, ir)))
    conv_kernel<0><<<dim3(BX, 2), 256, sm_big>>>(rgb, ir, w_off1, b_off1, nullptr, nullptr);
    // 2) offset/mask conv (27 ch)
    conv_kernel<3><<<dim3(BX, 1), 256, sm_off>>>(nullptr, nullptr, w_off2, b_off2, nullptr, nullptr);
    // 3) deformable bilinear sampling * mask -> g_vals
    deform_kernel<<<Bn * 9 * 27, 256>>>(ir);
    // 4) ir_aligned = vals . w_dcn + b_dcn (1x1 conv, Cin=1152, cp.async pipeline)
    dcn_conv_kernel<<<dim3(BX, 2), 256, DCN_SMEM>>>(w_dcn, b_dcn);
    // 5) gate stage 1
    gate1_kernel<<<(Bn * HW + 255) / 256, 256>>>(rgb, w_g1, bn_g1);
    // 6) gate stages 2+3
    gate23_kernel<<<(Bn * HW + 255) / 256, 256>>>(w_g2, bn_g2, w_g3, b_g3);
    // 7) fused conv + BN + SiLU + residual -> out
    conv_kernel<1><<<dim3(BX, 2), 256, sm_big>>>(rgb, nullptr, w_f, bn_f, rscale, out);
}

// round 6
// speedup vs baseline: 1.1569x; 1.0867x over previous
#include <cuda_runtime.h>

// ---------------------------------------------------------------------------
// Problem constants
// ---------------------------------------------------------------------------
constexpr int Bn  = 8;
constexpr int CH  = 128;
constexpr int H   = 80;
constexpr int W   = 80;
constexpr int HW  = H * W;
constexpr int MID = 16;
constexpr int KD  = CH * 9;          // 1152
constexpr float EPS = 1e-5f;

// ---------------------------------------------------------------------------
// Scratch
// ---------------------------------------------------------------------------
__device__ float g_h[Bn * CH * HW];
__device__ float g_off[Bn * 27 * HW];
__device__ float g_vals[(size_t)Bn * CH * 9 * HW];   // [b][c*9+k][y][x]
__device__ float g_iral[Bn * CH * HW];
__device__ float g_g1[Bn * MID * HW];
__device__ float g_gate[Bn * HW];
__device__ float g_fin[Bn * 2 * CH * HW];            // fused conv input concat

#define DEV __device__ __forceinline__
typedef unsigned long long ull;
typedef unsigned int u32;

DEV float sigm_(float x) { return 1.0f / (1.0f + __expf(-x)); }
DEV float silu_(float x) { return x * sigm_(x); }

DEV void ffma2(ull& d, ull a, ull b) {
    asm("fma.rn.f32x2 %0, %1, %2, %0;" : "+l"(d) : "l"(a), "l"(b));
}
DEV ull dup2(float w) { ull u; asm("mov.b64 %0, {%1, %1};" : "=l"(u) : "f"(w)); return u; }
DEV void unpack2(ull u, float& x, float& y) {
    asm("mov.b64 {%0, %1}, %2;" : "=f"(x), "=f"(y) : "l"(u));
}
DEV u32 smem_u32(const void* p) {
    u32 a; asm("{ .reg .u64 t; cvta.to.shared.u64 t, %1; cvt.u32.u64 %0, t; }" : "=r"(a) : "l"(p));
    return a;
}
DEV void cp4(u32 dst, const float* src) {
    asm volatile("cp.async.ca.shared.global [%0], [%1], 4;" :: "r"(dst), "l"(src) : "memory");
}
// zero-fill variant: src-size=0 -> no global read, smem gets zeros
DEV void cp4z(u32 dst, const float* src, bool ok) {
    int sz = ok ? 4 : 0;
    asm volatile("cp.async.ca.shared.global [%0], [%1], 4, %2;"
                 :: "r"(dst), "l"(src), "r"(sz) : "memory");
}
DEV void cp_commit() { asm volatile("cp.async.commit_group;" ::: "memory"); }
DEV void cp_wait1()  { asm volatile("cp.async.wait_group 1;" ::: "memory"); }
DEV void cp_wait0()  { asm volatile("cp.async.wait_group 0;" ::: "memory"); }

// ---------------------------------------------------------------------------
// 3x3 tiled conv, cp.async double-buffered staging, packed f32x2 math.
//   MODE 0: concat(rgb, ir)  Cin=256 -> g_h   (silu(v+b))
//   MODE 1: g_fin            Cin=256 -> out   (silu(bn)+res)
//   MODE 3: g_h              Cin=128 -> g_off (v+b)
// Block: 256 thr = 16 co-groups x 16 px-groups (5 px), 2 output rows.
// ---------------------------------------------------------------------------
template <int MODE>
__global__ __launch_bounds__(256)
void conv_kernel(const float* __restrict__ A, const float* __restrict__ Bp,
                 const float* __restrict__ wgt,
                 const float* __restrict__ bias_or_bn,
                 const float* __restrict__ res_scale,
                 float* __restrict__ out_param) {
    constexpr int KS2  = 9;
    constexpr int CIN  = (MODE == 3) ? CH : 2 * CH;
    constexpr int COUT = (MODE == 3) ? 27 : CH;
    constexpr int RCO  = (MODE == 3) ? 2 : 4;
    constexpr int CO_TILE = 16 * RCO;
    constexpr int CO_PAD  = CO_TILE + 4;
    constexpr int CC   = 8;                    // input-channel chunk
    constexpr int S    = CC * KS2;             // 72
    constexpr int XW   = W + 2;
    constexpr int SM_WF = S * CO_PAD;          // floats per weight buffer
    constexpr int SM_IF = CC * 3 * XW;         // float2 per input buffer
    constexpr int NCK  = CIN / CC;

    extern __shared__ float sm[];
    float*  sW = sm;                               // [2][SM_WF]
    float2* sI = (float2*)(sm + 2 * SM_WF);        // [2][SM_IF]

    const int tid = threadIdx.x;
    const int tco = tid & 15;
    const int tpx = tid >> 4;
    const int x0  = tpx * 5;
    const int b   = blockIdx.x / (H / 2);
    const int y0  = (blockIdx.x % (H / 2)) * 2;
    const int co_base = blockIdx.y * CO_TILE;

    const u32 swb = smem_u32(sW);
    const u32 sib = smem_u32(sI);

    ull acc[RCO][5];
#pragma unroll
    for (int r = 0; r < RCO; r++)
#pragma unroll
        for (int p = 0; p < 5; p++) acc[r][p] = 0ull;

    auto chan_ptr = [&](int ci) -> const float* {
        if (MODE == 0) return (ci < CH) ? A + (size_t)(b * CH + ci) * HW
                                        : Bp + (size_t)(b * CH + (ci - CH)) * HW;
        else if (MODE == 1) return g_fin + (size_t)(b * 2 * CH + ci) * HW;
        else return g_h + (size_t)(b * CH + ci) * HW;
    };

    auto stage = [&](int ck, int buf) {
        const int ci0 = ck * CC;
        // weights
        for (int idx = tid; idx < CO_TILE * S; idx += 256) {
            int co = idx / S;
            int s  = idx % S;
            int cog = co_base + co;
            u32 dst = swb + (u32)(buf * SM_WF + s * CO_PAD + co) * 4u;
            if (MODE == 3)
                cp4z(dst, wgt + (size_t)cog * (CIN * KS2) + ci0 * KS2 + s, cog < COUT);
            else
                cp4(dst, wgt + (size_t)cog * (CIN * KS2) + ci0 * KS2 + s);
        }
        // inputs (row-pair interleaved float2), zfill halo
        for (int idx = tid; idx < CC * 3 * XW; idx += 256) {
            int ci  = idx / (3 * XW);
            int rem = idx % (3 * XW);
            int ry  = rem / XW;
            int xx  = rem % XW;
            int gx  = xx - 1;
            int gy0 = y0 - 1 + ry;
            int gy1 = gy0 + 1;
            bool okx = (gx >= 0) && (gx < W);
            const float* src = chan_ptr(ci0 + ci) + gy0 * W + gx;
            u32 dst = sib + (u32)(buf * SM_IF + (ci * 3 + ry) * XW + xx) * 8u;
            cp4z(dst,     src,     okx && (gy0 >= 0) && (gy0 < H));
            cp4z(dst + 4, src + W, okx && (gy1 < H));
        }
        cp_commit();
    };

    stage(0, 0);

    for (int ck = 0; ck < NCK; ck++) {
        const int buf = ck & 1;
        if (ck + 1 < NCK) { stage(ck + 1, buf ^ 1); cp_wait1(); }
        else              { cp_wait0(); }
        __syncthreads();

        const float*  wbuf = sW + buf * SM_WF;
        const float2* ibuf = sI + buf * SM_IF;
        for (int ci = 0; ci < CC; ++ci) {
#pragma unroll
            for (int ky = 0; ky < 3; ky++) {
                const ull* ip = reinterpret_cast<const ull*>(&ibuf[(ci * 3 + ky) * XW + x0]);
                ull vv[7];
#pragma unroll
                for (int j = 0; j < 7; j++) vv[j] = ip[j];
#pragma unroll
                for (int kx = 0; kx < 3; kx++) {
                    const int s = ci * KS2 + ky * 3 + kx;
                    const float* wp = &wbuf[s * CO_PAD + tco * RCO];
                    ull w2[RCO];
                    if (RCO == 4) {
                        float4 w4 = *reinterpret_cast<const float4*>(wp);
                        w2[0] = dup2(w4.x); w2[1] = dup2(w4.y);
                        w2[2] = dup2(w4.z); w2[3] = dup2(w4.w);
                    } else {
                        float2 wv = *reinterpret_cast<const float2*>(wp);
                        w2[0] = dup2(wv.x); w2[1] = dup2(wv.y);
                    }
#pragma unroll
                    for (int p = 0; p < 5; p++)
#pragma unroll
                        for (int r = 0; r < RCO; r++) ffma2(acc[r][p], w2[r], vv[kx + p]);
                }
            }
        }
        __syncthreads();
    }

    float* optr = (MODE == 0) ? g_h : (MODE == 3) ? g_off : out_param;
#pragma unroll
    for (int r = 0; r < RCO; r++) {
        int co = co_base + tco * RCO + r;
        if (co >= COUT) continue;
        float bnb, bns = 1.0f, rs = 0.0f;
        if (MODE == 1) {
            float gm = bias_or_bn[co];
            float bt = bias_or_bn[COUT + co];
            float mn = bias_or_bn[2 * COUT + co];
            float vr = bias_or_bn[3 * COUT + co];
            bns = gm * rsqrtf(vr + EPS);
            bnb = bt - mn * bns;
            rs  = *res_scale;
        } else {
            bnb = bias_or_bn[co];
        }
#pragma unroll
        for (int p = 0; p < 5; p++) {
            int x = x0 + p;
            int o0 = ((b * COUT + co) * H + y0) * W + x;
            int o1 = o0 + W;
            float a0, a1;
            unpack2(acc[r][p], a0, a1);
            if (MODE == 0) {
                optr[o0] = silu_(a0 + bnb);
                optr[o1] = silu_(a1 + bnb);
            } else if (MODE == 1) {
                optr[o0] = silu_(a0 * bns + bnb) + rs * g_iral[o0];
                optr[o1] = silu_(a1 * bns + bnb) + rs * g_iral[o1];
            } else {
                optr[o0] = a0 + bnb;
                optr[o1] = a1 + bnb;
            }
        }
    }
}

// ---------------------------------------------------------------------------
// DCN 1x1 conv (Cin=1152 -> 128), cp.async double-buffered (R5, unchanged)
// ---------------------------------------------------------------------------
constexpr int DCC     = 32;
constexpr int DCO_T   = 64;
constexpr int DCO_PAD = 68;
constexpr int DWELEM  = DCO_T * DCC;
constexpr int DIELEM  = DCC * W;
constexpr int DSM_W   = DCC * DCO_PAD;
constexpr int DSM_I   = DCC * W;
constexpr int DCN_SMEM = (2 * DSM_W) * 4 + (2 * DSM_I) * 8;

__global__ __launch_bounds__(256)
void dcn_conv_kernel(const float* __restrict__ wgt,
                     const float* __restrict__ bias) {
    extern __shared__ float dsm[];
    float*  sW = dsm;
    float2* sI = (float2*)(dsm + 2 * DSM_W);

    const int tid = threadIdx.x;
    const int tco = tid & 15;
    const int tpx = tid >> 4;
    const int x0  = tpx * 5;
    const int b   = blockIdx.x / (H / 2);
    const int y0  = (blockIdx.x % (H / 2)) * 2;
    const int co_base = blockIdx.y * DCO_T;

    const u32 swb = smem_u32(sW);
    const u32 sib = smem_u32(sI);
    const float* vbase = g_vals + (size_t)b * KD * HW + (size_t)y0 * W;

    ull acc[4][5];
#pragma unroll
    for (int r = 0; r < 4; r++)
#pragma unroll
        for (int p = 0; p < 5; p++) acc[r][p] = 0ull;

    auto stage = [&](int ck, int buf) {
        const int ci0 = ck * DCC;
#pragma unroll
        for (int i = 0; i < DWELEM / 256; i++) {
            int idx = i * 256 + tid;
            int co = idx >> 5, s = idx & 31;
            u32 dst = swb + (u32)(buf * DSM_W + s * DCO_PAD + co) * 4u;
            cp4(dst, wgt + (size_t)(co_base + co) * KD + ci0 + s);
        }
#pragma unroll
        for (int i = 0; i < DIELEM / 256; i++) {
            int idx = i * 256 + tid;
            int ci = idx / W, xx = idx % W;
            const float* src = vbase + (size_t)(ci0 + ci) * HW + xx;
            u32 dst = sib + (u32)(buf * DSM_I + ci * W + xx) * 8u;
            cp4(dst, src);
            cp4(dst + 4, src + W);
        }
        cp_commit();
    };

    stage(0, 0);

    constexpr int NCK = KD / DCC;
    for (int ck = 0; ck < NCK; ck++) {
        const int buf = ck & 1;
        if (ck + 1 < NCK) { stage(ck + 1, buf ^ 1); cp_wait1(); }
        else              { cp_wait0(); }
        __syncthreads();

        const float*  wbuf = sW + buf * DSM_W;
        const float2* ibuf = sI + buf * DSM_I;
#pragma unroll 4
        for (int ci = 0; ci < DCC; ++ci) {
            const ull* ip = reinterpret_cast<const ull*>(&ibuf[ci * W + x0]);
            ull vv[5];
#pragma unroll
            for (int p = 0; p < 5; p++) vv[p] = ip[p];
            float4 w4 = *reinterpret_cast<const float4*>(&wbuf[ci * DCO_PAD + tco * 4]);
            ull w2[4] = { dup2(w4.x), dup2(w4.y), dup2(w4.z), dup2(w4.w) };
#pragma unroll
            for (int p = 0; p < 5; p++)
#pragma unroll
                for (int r = 0; r < 4; r++) ffma2(acc[r][p], w2[r], vv[p]);
        }
        __syncthreads();
    }

#pragma unroll
    for (int r = 0; r < 4; r++) {
        int co = co_base + tco * 4 + r;
        float bs = __ldg(&bias[co]);
#pragma unroll
        for (int p = 0; p < 5; p++) {
            int x = x0 + p;
            int o0 = ((b * CH + co) * H + y0) * W + x;
            float a0, a1;
            unpack2(acc[r][p], a0, a1);
            g_iral[o0]     = a0 + bs;
            g_iral[o0 + W] = a1 + bs;
        }
    }
}

// ---------------------------------------------------------------------------
// Deformable bilinear sampling -> g_vals[b][c*9+k][y][x]
// ---------------------------------------------------------------------------
__global__ __launch_bounds__(256)
void deform_kernel(const float* __restrict__ ir) {
    const int blk   = blockIdx.x;
    const int ytile = blk % 27;
    const int bk    = blk / 27;
    const int k     = bk % 9;
    const int b     = bk / 9;
    const int tid   = threadIdx.x;
    if (tid >= 240) return;
    const int y = ytile * 3 + tid / 80;
    const int x = tid % 80;
    if (y >= H) return;

    const float* obase = g_off + (b * 27) * HW + y * W + x;
    float oy = obase[(2 * k) * HW];
    float ox = obase[(2 * k + 1) * HW];
    float m  = sigm_(obase[(18 + k) * HW]);

    const int ky = k / 3 - 1;
    const int kx = k % 3 - 1;
    float ys = oy + (float)(ky + y);
    float xs = ox + (float)(kx + x);
    float fy = floorf(ys), fx = floorf(xs);
    float wy = ys - fy,    wx = xs - fx;
    int y0 = (int)fy, x0 = (int)fx;
    int y1 = y0 + 1,  x1 = x0 + 1;
    bool vy0 = (y0 >= 0) && (y0 < H);
    bool vy1 = (y1 >= 0) && (y1 < H);
    bool vx0 = (x0 >= 0) && (x0 < W);
    bool vx1 = (x1 >= 0) && (x1 < W);
    float w00 = (1.0f - wy) * (1.0f - wx) * m * ((vy0 && vx0) ? 1.0f : 0.0f);
    float w01 = (1.0f - wy) * wx          * m * ((vy0 && vx1) ? 1.0f : 0.0f);
    float w10 = wy          * (1.0f - wx) * m * ((vy1 && vx0) ? 1.0f : 0.0f);
    float w11 = wy          * wx          * m * ((vy1 && vx1) ? 1.0f : 0.0f);
    int cy0 = min(max(y0, 0), H - 1), cy1 = min(max(y1, 0), H - 1);
    int cx0 = min(max(x0, 0), W - 1), cx1 = min(max(x1, 0), W - 1);
    int i00 = cy0 * W + cx0, i01 = cy0 * W + cx1;
    int i10 = cy1 * W + cx0, i11 = cy1 * W + cx1;

    const float* ib = ir + b * CH * HW;
    float* vout = g_vals + ((size_t)b * CH * 9 + k) * HW + y * W + x;
#pragma unroll 4
    for (int c = 0; c < CH; c++) {
        const float* p = ib + c * HW;
        float v = w00 * __ldg(p + i00) + w01 * __ldg(p + i01)
                + w10 * __ldg(p + i10) + w11 * __ldg(p + i11);
        vout[(size_t)c * 9 * HW] = v;
    }
}

// ---------------------------------------------------------------------------
// Gate stage 1: 1x1 conv 256 -> 16 + BN + SiLU -> g_g1
// ---------------------------------------------------------------------------
__global__ __launch_bounds__(256)
void gate1_kernel(const float* __restrict__ rgb,
                  const float* __restrict__ wg1,
                  const float* __restrict__ bng1) {
    __shared__ float sg[2 * CH * MID];
    const int tid = threadIdx.x;
    for (int i = tid; i < 2 * CH * MID; i += 256) {
        int ci = i >> 4, o = i & 15;
        sg[i] = wg1[o * (2 * CH) + ci];
    }
    __syncthreads();
    const int idx = blockIdx.x * 256 + tid;
    if (idx >= Bn * HW) return;
    const int b = idx / HW, p = idx % HW;

    float acc[MID];
#pragma unroll
    for (int o = 0; o < MID; o++) acc[o] = 0.0f;

    const float* rp = rgb    + b * CH * HW + p;
    const float* ip = g_iral + b * CH * HW + p;
    for (int ci = 0; ci < CH; ci++) {
        float v = rp[ci * HW];
        const float* w = &sg[ci * MID];
#pragma unroll
        for (int o = 0; o < MID; o++) acc[o] += w[o] * v;
    }
    for (int ci = 0; ci < CH; ci++) {
        float v = ip[ci * HW];
        const float* w = &sg[(CH + ci) * MID];
#pragma unroll
        for (int o = 0; o < MID; o++) acc[o] += w[o] * v;
    }
#pragma unroll
    for (int o = 0; o < MID; o++) {
        float gm = bng1[o], bt = bng1[MID + o];
        float mn = bng1[2 * MID + o], vr = bng1[3 * MID + o];
        float sc = gm * rsqrtf(vr + EPS);
        g_g1[(b * MID + o) * HW + p] = silu_(acc[o] * sc + bt - mn * sc);
    }
}

// ---------------------------------------------------------------------------
// Gate stages 2+3, then materialize fused conv input g_fin
// ---------------------------------------------------------------------------
__global__ __launch_bounds__(256)
void gate23_kernel(const float* __restrict__ wg2,
                   const float* __restrict__ bng2,
                   const float* __restrict__ wg3,
                   const float* __restrict__ bg3,
                   const float* __restrict__ rgb) {
    const int idx = blockIdx.x * 256 + threadIdx.x;
    if (idx >= Bn * HW) return;
    const int b = idx / HW, p = idx % HW;
    const int y = p / W, x = p % W;

    float s3 = __ldg(bg3);
#pragma unroll
    for (int o = 0; o < MID; o++) {
        const float* gp = g_g1 + (b * MID + o) * HW;
        float s = 0.0f;
#pragma unroll
        for (int ky = 0; ky < 3; ky++) {
            int yy = y + ky - 1;
            if (yy < 0 || yy >= H) continue;
#pragma unroll
            for (int kx = 0; kx < 3; kx++) {
                int xx = x + kx - 1;
                if (xx < 0 || xx >= W) continue;
                s += gp[yy * W + xx] * __ldg(&wg2[o * 9 + ky * 3 + kx]);
            }
        }
        float gm = __ldg(&bng2[o]), bt = __ldg(&bng2[MID + o]);
        float mn = __ldg(&bng2[2 * MID + o]), vr = __ldg(&bng2[3 * MID + o]);
        float sc = gm * rsqrtf(vr + EPS);
        s3 += silu_(s * sc + bt - mn * sc) * __ldg(&wg3[o]);
    }
    float gv = sigm_(s3);
    g_gate[b * HW + p] = gv;

    // materialize fused conv input: [g*iral, (1-g)*rgb]
    const float* ip = g_iral + (size_t)b * CH * HW + p;
    const float* rp = rgb    + (size_t)b * CH * HW + p;
    float* f0 = g_fin + (size_t)b * 2 * CH * HW + p;
    float* f1 = f0 + (size_t)CH * HW;
    float om = 1.0f - gv;
#pragma unroll 4
    for (int c = 0; c < CH; c++) {
        f0[(size_t)c * HW] = gv * ip[(size_t)c * HW];
        f1[(size_t)c * HW] = om * rp[(size_t)c * HW];
    }
}

// ---------------------------------------------------------------------------
// Launcher
// ---------------------------------------------------------------------------
extern "C" void kernel_launch(void* const* d_in, const int* in_sizes, int n_in,
                              void* d_out, int out_size) {
    const float* rgb    = (const float*)d_in[0];
    const float* ir     = (const float*)d_in[1];
    const float* w_off1 = (const float*)d_in[2];
    const float* b_off1 = (const float*)d_in[3];
    const float* w_off2 = (const float*)d_in[4];
    const float* b_off2 = (const float*)d_in[5];
    const float* w_dcn  = (const float*)d_in[6];
    const float* b_dcn  = (const float*)d_in[7];
    const float* w_g1   = (const float*)d_in[8];
    const float* bn_g1  = (const float*)d_in[9];
    const float* w_g2   = (const float*)d_in[10];
    const float* bn_g2  = (const float*)d_in[11];
    const float* w_g3   = (const float*)d_in[12];
    const float* b_g3   = (const float*)d_in[13];
    const float* w_f    = (const float*)d_in[14];
    const float* bn_f   = (const float*)d_in[15];
    const float* rscale = (const float*)d_in[16];
    float* out = (float*)d_out;

    // double-buffered smem sizes
    const int sm_big = 2 * ((72 * 68) * 4 + (8 * 3 * 82) * 8);   // 70656 B (modes 0,1)
    const int sm_off = 2 * ((72 * 36) * 4 + (8 * 3 * 82) * 8);   // 52224 B (mode 3)

    cudaFuncSetAttribute(conv_kernel<0>, cudaFuncAttributeMaxDynamicSharedMemorySize, sm_big);
    cudaFuncSetAttribute(conv_kernel<1>, cudaFuncAttributeMaxDynamicSharedMemorySize, sm_big);
    cudaFuncSetAttribute(conv_kernel<3>, cudaFuncAttributeMaxDynamicSharedMemorySize, sm_off);
    cudaFuncSetAttribute(dcn_conv_kernel, cudaFuncAttributeMaxDynamicSharedMemorySize, DCN_SMEM);

    const int BX = Bn * (H / 2);   // 320 row-pair blocks

    // 1) h = silu(conv3x3(concat(rgb, ir)))
    conv_kernel<0><<<dim3(BX, 2), 256, sm_big>>>(rgb, ir, w_off1, b_off1, nullptr, nullptr);
    // 2) offset/mask conv (27 ch)
    conv_kernel<3><<<dim3(BX, 1), 256, sm_off>>>(nullptr, nullptr, w_off2, b_off2, nullptr, nullptr);
    // 3) deformable bilinear sampling * mask -> g_vals
    deform_kernel<<<Bn * 9 * 27, 256>>>(ir);
    // 4) ir_aligned = vals . w_dcn + b_dcn
    dcn_conv_kernel<<<dim3(BX, 2), 256, DCN_SMEM>>>(w_dcn, b_dcn);
    // 5) gate stage 1
    gate1_kernel<<<(Bn * HW + 255) / 256, 256>>>(rgb, w_g1, bn_g1);
    // 6) gate stages 2+3 + fused-input materialization
    gate23_kernel<<<(Bn * HW + 255) / 256, 256>>>(w_g2, bn_g2, w_g3, b_g3, rgb);
    // 7) fused conv + BN + SiLU + residual -> out
    conv_kernel<1><<<dim3(BX, 2), 256, sm_big>>>(nullptr, nullptr, w_f, bn_f, rscale, out);
}